// round 10
// baseline (speedup 1.0000x reference)
#include <cuda_runtime.h>
#include <cstdint>

#define D_LEN 32768

// ---------------- scratch (static device globals, no allocation) ------------
__device__ __align__(256) float g_a[64 * D_LEN];
__device__ __align__(256) float g_s[64 * D_LEN];
__device__ __align__(256) float g_c[64 * D_LEN];
__device__ double g_part[1280];

__constant__ int c_PI[10] = {0,0,0,0,1,1,1,2,2,3};
__constant__ int c_PJ[10] = {0,1,2,3,1,2,3,2,3,3};

// ---------------- fast fp32 sincos(x), |x| <~ 1000 --------------------------
__device__ __forceinline__ void sincos_fast(float x, float& s_out, float& c_out) {
    const float PIO2_A = 1.5707963705062866f;      // RN(pi/2)
    const float PIO2_B = -4.3711388286737929e-8f;  // pi/2 - PIO2_A
    float q = rintf(x * 0.63661977236758134f);     // 2/pi
    int qi = (int)q;
    float r = fmaf(q, -PIO2_A, x);
    r = fmaf(q, -PIO2_B, r);
    float z = r * r;
    float ps = fmaf(z, fmaf(z, -1.9515295891e-4f, 8.3321608736e-3f), -1.6666654611e-1f);
    float sinr = fmaf(r * z, ps, r);
    float pc = fmaf(z, fmaf(z, 2.443315711809948e-5f, -1.388731625493765e-3f),
                    4.166664568298827e-2f);
    float cosr = fmaf(z * z, pc, fmaf(z, -0.5f, 1.0f));
    float s, c;
    if (qi & 1) { s = cosr; c = -sinr; } else { s = sinr; c = cosr; }
    if (qi & 2) { s = -s; c = -c; }
    s_out = s; c_out = c;
}

// ---------------- pool(4) + sincos(100*m), 4 outputs/thread -----------------
__global__ void pool_kernel(const float* __restrict__ A, const float* __restrict__ B) {
    int idx = blockIdx.x * blockDim.x + threadIdx.x;   // [0, 524288)
    int tensor = idx >> 18;
    int rem = idx & 262143;
    int b  = rem >> 13;                                // 0..31
    int fg = rem & 8191;                               // feat group (4 feats)
    int c   = fg >> 6;
    int ph  = (fg >> 2) & 15;
    int pw0 = (fg & 3) * 4;
    const float* src = tensor ? B : A;
    const float* p = src + ((((b * 128 + c) * 64) + ph * 4) * 64 + pw0 * 4);

    float s0 = 0.f, s1 = 0.f, s2 = 0.f, s3 = 0.f;
    #pragma unroll
    for (int r = 0; r < 4; ++r) {
        const float* q = p + r * 64;
        float4 v0 = __ldcs((const float4*)(q));
        float4 v1 = __ldcs((const float4*)(q + 4));
        float4 v2 = __ldcs((const float4*)(q + 8));
        float4 v3 = __ldcs((const float4*)(q + 12));
        s0 += (v0.x + v0.y) + (v0.z + v0.w);
        s1 += (v1.x + v1.y) + (v1.z + v1.w);
        s2 += (v2.x + v2.y) + (v2.z + v2.w);
        s3 += (v3.x + v3.y) + (v3.z + v3.w);
    }
    float4 m = make_float4(s0 * 0.0625f, s1 * 0.0625f, s2 * 0.0625f, s3 * 0.0625f);
    float4 sv, cv;
    sincos_fast(100.0f * m.x, sv.x, cv.x);
    sincos_fast(100.0f * m.y, sv.y, cv.y);
    sincos_fast(100.0f * m.z, sv.z, cv.z);
    sincos_fast(100.0f * m.w, sv.w, cv.w);

    int row = tensor * 32 + b;
    int off = row * D_LEN + fg * 4;
    *(float4*)(g_a + off) = m;
    *(float4*)(g_s + off) = sv;
    *(float4*)(g_c + off) = cv;
}

// ---------------- pair kernel ------------------------------------------------
__device__ __forceinline__ void cp16(uint32_t dst, const float* src) {
    asm volatile("cp.async.cg.shared.global [%0], [%1], 16;\n" :: "r"(dst), "l"(src));
}
__device__ __forceinline__ float frcp(float x) {
    float r; asm("rcp.approx.ftz.f32 %0, %1;" : "=f"(r) : "f"(x)); return r;
}
__device__ __forceinline__ float wgt(int u, int v, bool diag) {
    if (diag && u >= v) return 0.0f;
    return ((u < 32) == (v < 32)) ? 1.0f : -1.0f;
}

// Pairwise reciprocal: 2 terms share one rcp.
//   w = rcp(d0*d1);  acc += (n0*d1 + n1*d0) * w
// If D==0 the pair is skipped (expected ~4 events total, <=2.4e-5 abs on a
// ~6.25 result -- negligible vs 1e-3 tolerance).
#define TERM2P(AU0,SU0,CU0,AV0,SV0,CV0,AU1,SU1,CU1,AV1,SV1,CV1,ACC) do { \
    float d0_ = (AU0) - (AV0);                                 \
    float d1_ = (AU1) - (AV1);                                 \
    float D_  = d0_ * d1_;                                     \
    float w_  = frcp(D_);                                      \
    float t0_ = (CU0) * (SV0);                                 \
    float n0_ = fmaf((SU0), (CV0), -t0_);                      \
    float t1_ = (CU1) * (SV1);                                 \
    float n1_ = fmaf((SU1), (CV1), -t1_);                      \
    float s_  = n0_ * d1_;                                     \
    s_ = fmaf(n1_, d0_, s_);                                   \
    if (D_ != 0.0f) (ACC) = fmaf(s_, w_, (ACC));               \
} while (0)

#define TERM4(AU,SU,CU,AV,SV,CV,ACC) do {                      \
    TERM2P((AU).x,(SU).x,(CU).x,(AV).x,(SV).x,(CV).x,          \
           (AU).y,(SU).y,(CU).y,(AV).y,(SV).y,(CV).y,(ACC));   \
    TERM2P((AU).z,(SU).z,(CU).z,(AV).z,(SV).z,(CV).z,          \
           (AU).w,(SU).w,(CU).w,(AV).w,(SV).w,(CV).w,(ACC));   \
} while (0)

// Padded smem layout: 64 data floats/row + 8 pad => ROWSTR 72 (72 mod 32 = 8).
// Per LDS.128: 8 distinct bank-quads x 4-way broadcast -> conflict-free.
#define ROWSTR 72
#define ARRSTR 1152           /* 16*72 */
#define BUFSTR 6912           /* 6*1152 floats; 27648 B per buffer */
#define KSTAGE 64
#define NSTAGE 4              /* 256 k per block */

__global__ void __launch_bounds__(256, 3) pair_kernel() {
    __shared__ __align__(16) float smem[2 * BUFSTR];
    __shared__ double red[8];
    const int tid = threadIdx.x;
    const int pidx = blockIdx.y;
    const int I = c_PI[pidx], J = c_PJ[pidx];
    const int Ibase = I * 16, Jbase = J * 16;
    const int k0 = blockIdx.x * (KSTAGE * NSTAGE);
    const uint32_t sbase = (uint32_t)__cvta_generic_to_shared(smem);

    const float* srcs[6];
    srcs[0] = g_a + Ibase * D_LEN;
    srcs[1] = g_s + Ibase * D_LEN;
    srcs[2] = g_c + Ibase * D_LEN;
    srcs[3] = g_a + Jbase * D_LEN;
    srcs[4] = g_s + Jbase * D_LEN;
    srcs[5] = g_c + Jbase * D_LEN;

    // loader mapping: 1536 float4 per stage = 6 per thread (one per array)
    const int lrow  = tid >> 4;          // 0..15
    const int lslot = tid & 15;          // 0..15
    const int lsoff = lrow * ROWSTR + lslot * 4;
    const int lgoff = lrow * D_LEN + k0 + lslot * 4;

    #pragma unroll
    for (int j = 0; j < 6; ++j)
        cp16(sbase + 4 * (j * ARRSTR + lsoff), srcs[j] + lgoff);
    asm volatile("cp.async.commit_group;\n");

    // compute mapping: kq 16-way k split, 4x4 register tile over rows
    const int kq = tid >> 4;             // 0..15 -> float4 slot
    const int tu = (tid >> 2) & 3;       // 0..3
    const int tv = tid & 3;              // 0..3
    float acc[4][4];
    #pragma unroll
    for (int i = 0; i < 4; ++i)
        #pragma unroll
        for (int j = 0; j < 4; ++j) acc[i][j] = 0.0f;

    for (int st = 0; st < NSTAGE; ++st) {
        const int buf = st & 1;
        if (st + 1 < NSTAGE) {
            const int nb = buf ^ 1;
            #pragma unroll
            for (int j = 0; j < 6; ++j)
                cp16(sbase + 4 * (nb * BUFSTR + j * ARRSTR + lsoff),
                     srcs[j] + lgoff + (st + 1) * KSTAGE);
            asm volatile("cp.async.commit_group;\n");
            asm volatile("cp.async.wait_group 1;\n");
        } else {
            asm volatile("cp.async.wait_group 0;\n");
        }
        __syncthreads();

        const float* base = smem + buf * BUFSTR + kq * 4;

        // loop interchange: one v column and one u row live at a time
        // (low register footprint -> occupancy 3 without spills)
        #pragma unroll
        for (int j = 0; j < 4; ++j) {
            const int vo = (tv + 4 * j) * ROWSTR;
            float4 av = *(const float4*)(base + 3 * ARRSTR + vo);
            float4 sv = *(const float4*)(base + 4 * ARRSTR + vo);
            float4 cv = *(const float4*)(base + 5 * ARRSTR + vo);
            #pragma unroll
            for (int i = 0; i < 4; ++i) {
                const int uo = (tu + 4 * i) * ROWSTR;
                float4 au = *(const float4*)(base + uo);
                float4 su = *(const float4*)(base + ARRSTR + uo);
                float4 cu = *(const float4*)(base + 2 * ARRSTR + uo);
                TERM4(au, su, cu, av, sv, cv, acc[i][j]);
            }
        }
        __syncthreads();
    }

    // weights (diagonal tile-pairs count only u<v; cross-tensor sign -1)
    const bool diag = (I == J);
    float tot = 0.0f;
    #pragma unroll
    for (int i = 0; i < 4; ++i) {
        const int u = Ibase + tu + 4 * i;
        #pragma unroll
        for (int j = 0; j < 4; ++j) {
            const int v = Jbase + tv + 4 * j;
            tot += wgt(u, v, diag) * acc[i][j];
        }
    }

    // deterministic block reduction in double
    double td = (double)tot;
    #pragma unroll
    for (int off = 16; off; off >>= 1)
        td += __shfl_down_sync(0xffffffffu, td, off);
    const int warp = tid >> 5, lane = tid & 31;
    if (lane == 0) red[warp] = td;
    __syncthreads();
    if (tid == 0) {
        double ss = 0.0;
        #pragma unroll
        for (int i = 0; i < 8; ++i) ss += red[i];
        g_part[blockIdx.y * 128 + blockIdx.x] = ss;
    }
}

// ---------------- final deterministic reduction ------------------------------
__global__ void final_kernel(float* __restrict__ out) {
    const int tid = threadIdx.x;
    double s = 0.0;
    for (int i = tid; i < 1280; i += 256) s += g_part[i];
    #pragma unroll
    for (int off = 16; off; off >>= 1)
        s += __shfl_down_sync(0xffffffffu, s, off);
    __shared__ double red[8];
    if ((tid & 31) == 0) red[tid >> 5] = s;
    __syncthreads();
    if (tid == 0) {
        double t = 0.0;
        #pragma unroll
        for (int i = 0; i < 8; ++i) t += red[i];
        out[0] = (float)(6.25 + t * (2.0 / 33554432.0));
    }
}

// ---------------- launch ------------------------------------------------------
extern "C" void kernel_launch(void* const* d_in, const int* in_sizes, int n_in,
                              void* d_out, int out_size) {
    (void)in_sizes; (void)n_in; (void)out_size;
    const float* A = (const float*)d_in[0];
    const float* B = (const float*)d_in[1];
    pool_kernel<<<2048, 256>>>(A, B);
    pair_kernel<<<dim3(128, 10), 256>>>();
    final_kernel<<<1, 256>>>((float*)d_out);
}

// round 11
// speedup vs baseline: 1.0276x; 1.0276x over previous
#include <cuda_runtime.h>
#include <cstdint>

#define D_LEN 32768
#define NBLK  2560            /* 256 k-chunks x 10 tile-pairs */

// ---------------- scratch (static device globals, no allocation) ------------
__device__ __align__(256) float g_a[64 * D_LEN];
__device__ __align__(256) float g_s[64 * D_LEN];
__device__ __align__(256) float g_c[64 * D_LEN];
__device__ double g_part[NBLK];
__device__ unsigned g_ctr = 0;   // atomicInc-wrap -> returns to 0 every launch

__constant__ int c_PI[10] = {0,0,0,0,1,1,1,2,2,3};
__constant__ int c_PJ[10] = {0,1,2,3,1,2,3,2,3,3};

// ---------------- fast fp32 sincos(x), |x| <~ 1000 --------------------------
__device__ __forceinline__ void sincos_fast(float x, float& s_out, float& c_out) {
    const float PIO2_A = 1.5707963705062866f;      // RN(pi/2)
    const float PIO2_B = -4.3711388286737929e-8f;  // pi/2 - PIO2_A
    float q = rintf(x * 0.63661977236758134f);     // 2/pi
    int qi = (int)q;
    float r = fmaf(q, -PIO2_A, x);
    r = fmaf(q, -PIO2_B, r);
    float z = r * r;
    float ps = fmaf(z, fmaf(z, -1.9515295891e-4f, 8.3321608736e-3f), -1.6666654611e-1f);
    float sinr = fmaf(r * z, ps, r);
    float pc = fmaf(z, fmaf(z, 2.443315711809948e-5f, -1.388731625493765e-3f),
                    4.166664568298827e-2f);
    float cosr = fmaf(z * z, pc, fmaf(z, -0.5f, 1.0f));
    float s, c;
    if (qi & 1) { s = cosr; c = -sinr; } else { s = sinr; c = cosr; }
    if (qi & 2) { s = -s; c = -c; }
    s_out = s; c_out = c;
}

// ---------------- pool(4) + sincos(100*m), 4 outputs/thread -----------------
__global__ void pool_kernel(const float* __restrict__ A, const float* __restrict__ B) {
    int idx = blockIdx.x * blockDim.x + threadIdx.x;   // [0, 524288)
    int tensor = idx >> 18;
    int rem = idx & 262143;
    int b  = rem >> 13;                                // 0..31
    int fg = rem & 8191;                               // feat group (4 feats)
    int c   = fg >> 6;
    int ph  = (fg >> 2) & 15;
    int pw0 = (fg & 3) * 4;
    const float* src = tensor ? B : A;
    const float* p = src + ((((b * 128 + c) * 64) + ph * 4) * 64 + pw0 * 4);

    float s0 = 0.f, s1 = 0.f, s2 = 0.f, s3 = 0.f;
    #pragma unroll
    for (int r = 0; r < 4; ++r) {
        const float* q = p + r * 64;
        float4 v0 = __ldcs((const float4*)(q));
        float4 v1 = __ldcs((const float4*)(q + 4));
        float4 v2 = __ldcs((const float4*)(q + 8));
        float4 v3 = __ldcs((const float4*)(q + 12));
        s0 += (v0.x + v0.y) + (v0.z + v0.w);
        s1 += (v1.x + v1.y) + (v1.z + v1.w);
        s2 += (v2.x + v2.y) + (v2.z + v2.w);
        s3 += (v3.x + v3.y) + (v3.z + v3.w);
    }
    float4 m = make_float4(s0 * 0.0625f, s1 * 0.0625f, s2 * 0.0625f, s3 * 0.0625f);
    float4 sv, cv;
    sincos_fast(100.0f * m.x, sv.x, cv.x);
    sincos_fast(100.0f * m.y, sv.y, cv.y);
    sincos_fast(100.0f * m.z, sv.z, cv.z);
    sincos_fast(100.0f * m.w, sv.w, cv.w);

    int row = tensor * 32 + b;
    int off = row * D_LEN + fg * 4;
    *(float4*)(g_a + off) = m;
    *(float4*)(g_s + off) = sv;
    *(float4*)(g_c + off) = cv;
}

// ---------------- pair kernel ------------------------------------------------
__device__ __forceinline__ void cp16(uint32_t dst, const float* src) {
    asm volatile("cp.async.cg.shared.global [%0], [%1], 16;\n" :: "r"(dst), "l"(src));
}
__device__ __forceinline__ float frcp(float x) {
    float r; asm("rcp.approx.ftz.f32 %0, %1;" : "=f"(r) : "f"(x)); return r;
}
__device__ __forceinline__ float wgt(int u, int v, bool diag) {
    if (diag && u >= v) return 0.0f;
    return ((u < 32) == (v < 32)) ? 1.0f : -1.0f;
}

// Pairwise reciprocal: 2 terms share one rcp.
//   w = rcp(d0*d1);  acc += (n0*d1 + n1*d0) * w
// If D==0 the pair is skipped (expected ~4 events total, <=2.4e-5 abs on a
// ~6.25 result -- negligible vs 1e-3 tolerance).
#define TERM2P(AU0,SU0,CU0,AV0,SV0,CV0,AU1,SU1,CU1,AV1,SV1,CV1,ACC) do { \
    float d0_ = (AU0) - (AV0);                                 \
    float d1_ = (AU1) - (AV1);                                 \
    float D_  = d0_ * d1_;                                     \
    float w_  = frcp(D_);                                      \
    float t0_ = (CU0) * (SV0);                                 \
    float n0_ = fmaf((SU0), (CV0), -t0_);                      \
    float t1_ = (CU1) * (SV1);                                 \
    float n1_ = fmaf((SU1), (CV1), -t1_);                      \
    float s_  = n0_ * d1_;                                     \
    s_ = fmaf(n1_, d0_, s_);                                   \
    if (D_ != 0.0f) (ACC) = fmaf(s_, w_, (ACC));               \
} while (0)

#define TERM4(AU,SU,CU,AV,SV,CV,ACC) do {                      \
    TERM2P((AU).x,(SU).x,(CU).x,(AV).x,(SV).x,(CV).x,          \
           (AU).y,(SU).y,(CU).y,(AV).y,(SV).y,(CV).y,(ACC));   \
    TERM2P((AU).z,(SU).z,(CU).z,(AV).z,(SV).z,(CV).z,          \
           (AU).w,(SU).w,(CU).w,(AV).w,(SV).w,(CV).w,(ACC));   \
} while (0)

// Padded smem layout: 64 data floats/row + 8 pad => ROWSTR 72 (72 mod 32 = 8).
// Per LDS.128: 8 distinct bank-quads x 4-way broadcast -> conflict-free.
#define ROWSTR 72
#define ARRSTR 1152           /* 16*72 */
#define BUFSTR 6912           /* 6*1152 floats; 27648 B per buffer */
#define KSTAGE 64
#define NSTAGE 2              /* 128 k per block */

__global__ void __launch_bounds__(256, 2) pair_kernel(float* __restrict__ out) {
    __shared__ __align__(16) float smem[2 * BUFSTR];
    __shared__ double red[8];
    __shared__ int s_last;
    const int tid = threadIdx.x;
    const int pidx = blockIdx.y;
    const int I = c_PI[pidx], J = c_PJ[pidx];
    const int Ibase = I * 16, Jbase = J * 16;
    const int k0 = blockIdx.x * (KSTAGE * NSTAGE);
    const uint32_t sbase = (uint32_t)__cvta_generic_to_shared(smem);

    const float* srcs[6];
    srcs[0] = g_a + Ibase * D_LEN;
    srcs[1] = g_s + Ibase * D_LEN;
    srcs[2] = g_c + Ibase * D_LEN;
    srcs[3] = g_a + Jbase * D_LEN;
    srcs[4] = g_s + Jbase * D_LEN;
    srcs[5] = g_c + Jbase * D_LEN;

    // loader mapping: 1536 float4 per stage = 6 per thread (one per array)
    const int lrow  = tid >> 4;          // 0..15
    const int lslot = tid & 15;          // 0..15
    const int lsoff = lrow * ROWSTR + lslot * 4;
    const int lgoff = lrow * D_LEN + k0 + lslot * 4;

    #pragma unroll
    for (int j = 0; j < 6; ++j)
        cp16(sbase + 4 * (j * ARRSTR + lsoff), srcs[j] + lgoff);
    asm volatile("cp.async.commit_group;\n");

    // compute mapping: kq 16-way k split, 4x4 register tile over rows
    const int kq = tid >> 4;             // 0..15 -> float4 slot
    const int tu = (tid >> 2) & 3;       // 0..3
    const int tv = tid & 3;              // 0..3
    float acc[4][4];
    #pragma unroll
    for (int i = 0; i < 4; ++i)
        #pragma unroll
        for (int j = 0; j < 4; ++j) acc[i][j] = 0.0f;

    for (int st = 0; st < NSTAGE; ++st) {
        const int buf = st & 1;
        if (st + 1 < NSTAGE) {
            const int nb = buf ^ 1;
            #pragma unroll
            for (int j = 0; j < 6; ++j)
                cp16(sbase + 4 * (nb * BUFSTR + j * ARRSTR + lsoff),
                     srcs[j] + lgoff + (st + 1) * KSTAGE);
            asm volatile("cp.async.commit_group;\n");
            asm volatile("cp.async.wait_group 1;\n");
        } else {
            asm volatile("cp.async.wait_group 0;\n");
        }
        __syncthreads();

        const float* base = smem + buf * BUFSTR + kq * 4;

        float4 av[4], sv[4], cv[4];
        #pragma unroll
        for (int j = 0; j < 4; ++j) {
            const int vo = (tv + 4 * j) * ROWSTR;
            av[j] = *(const float4*)(base + 3 * ARRSTR + vo);
            sv[j] = *(const float4*)(base + 4 * ARRSTR + vo);
            cv[j] = *(const float4*)(base + 5 * ARRSTR + vo);
        }
        #pragma unroll
        for (int i = 0; i < 4; ++i) {
            const int uo = (tu + 4 * i) * ROWSTR;
            float4 au = *(const float4*)(base + uo);
            float4 su = *(const float4*)(base + ARRSTR + uo);
            float4 cu = *(const float4*)(base + 2 * ARRSTR + uo);
            #pragma unroll
            for (int j = 0; j < 4; ++j)
                TERM4(au, su, cu, av[j], sv[j], cv[j], acc[i][j]);
        }
        __syncthreads();
    }

    // weights (diagonal tile-pairs count only u<v; cross-tensor sign -1)
    const bool diag = (I == J);
    float tot = 0.0f;
    #pragma unroll
    for (int i = 0; i < 4; ++i) {
        const int u = Ibase + tu + 4 * i;
        #pragma unroll
        for (int j = 0; j < 4; ++j) {
            const int v = Jbase + tv + 4 * j;
            tot += wgt(u, v, diag) * acc[i][j];
        }
    }

    // deterministic block reduction in double
    double td = (double)tot;
    #pragma unroll
    for (int off = 16; off; off >>= 1)
        td += __shfl_down_sync(0xffffffffu, td, off);
    const int warp = tid >> 5, lane = tid & 31;
    if (lane == 0) red[warp] = td;
    __syncthreads();
    if (tid == 0) {
        double ss = 0.0;
        #pragma unroll
        for (int i = 0; i < 8; ++i) ss += red[i];
        g_part[blockIdx.y * 256 + blockIdx.x] = ss;
        __threadfence();
        unsigned old = atomicInc(&g_ctr, NBLK - 1);   // wraps to 0 -> replay-safe
        s_last = (old == NBLK - 1) ? 1 : 0;
    }
    __syncthreads();

    // last-arriving block performs the final fixed-order reduction
    if (s_last) {
        double s = 0.0;
        for (int i = tid; i < NBLK; i += 256) s += g_part[i];
        #pragma unroll
        for (int off = 16; off; off >>= 1)
            s += __shfl_down_sync(0xffffffffu, s, off);
        if (lane == 0) red[warp] = s;
        __syncthreads();
        if (tid == 0) {
            double t = 0.0;
            #pragma unroll
            for (int i = 0; i < 8; ++i) t += red[i];
            // result = 6.25 (diagonal, 2*32*T/1024) + 2/(1024*D) * signed sum
            out[0] = (float)(6.25 + t * (2.0 / 33554432.0));
        }
    }
}

// ---------------- launch ------------------------------------------------------
extern "C" void kernel_launch(void* const* d_in, const int* in_sizes, int n_in,
                              void* d_out, int out_size) {
    (void)in_sizes; (void)n_in; (void)out_size;
    const float* A = (const float*)d_in[0];
    const float* B = (const float*)d_in[1];
    pool_kernel<<<2048, 256>>>(A, B);
    pair_kernel<<<dim3(256, 10), 256>>>((float*)d_out);
}

// round 12
// speedup vs baseline: 1.3289x; 1.2932x over previous
#include <cuda_runtime.h>
#include <cstdint>

#define NBLK   256            /* one block per 128-k chunk */
#define KCH    128
#define ROWSTR 136            /* 128 data + 8 pad; 136 mod 32 = 8 -> conflict-free */
#define ARRSTR (64 * ROWSTR)  /* 8704 floats per array */
#define SMEM_BYTES (3 * ARRSTR * 4)   /* 104448 B: a, s, c for 64 rows x 128 k */

__device__ double g_part[NBLK];
__device__ unsigned g_ctr = 0;   // atomicInc wraps back to 0 -> graph-replay safe

__constant__ int c_PI[10] = {0,0,0,0,1,1,1,2,2,3};
__constant__ int c_PJ[10] = {0,1,2,3,1,2,3,2,3,3};

// ---------------- fast fp32 sincos(x), |x| <~ 1000 --------------------------
__device__ __forceinline__ void sincos_fast(float x, float& s_out, float& c_out) {
    const float PIO2_A = 1.5707963705062866f;      // RN(pi/2)
    const float PIO2_B = -4.3711388286737929e-8f;  // pi/2 - PIO2_A
    float q = rintf(x * 0.63661977236758134f);     // 2/pi
    int qi = (int)q;
    float r = fmaf(q, -PIO2_A, x);
    r = fmaf(q, -PIO2_B, r);
    float z = r * r;
    float ps = fmaf(z, fmaf(z, -1.9515295891e-4f, 8.3321608736e-3f), -1.6666654611e-1f);
    float sinr = fmaf(r * z, ps, r);
    float pc = fmaf(z, fmaf(z, 2.443315711809948e-5f, -1.388731625493765e-3f),
                    4.166664568298827e-2f);
    float cosr = fmaf(z * z, pc, fmaf(z, -0.5f, 1.0f));
    float s, c;
    if (qi & 1) { s = cosr; c = -sinr; } else { s = sinr; c = cosr; }
    if (qi & 2) { s = -s; c = -c; }
    s_out = s; c_out = c;
}

__device__ __forceinline__ float frcp(float x) {
    float r; asm("rcp.approx.ftz.f32 %0, %1;" : "=f"(r) : "f"(x)); return r;
}
__device__ __forceinline__ float wgt(int u, int v, bool diag) {
    if (diag && u >= v) return 0.0f;
    return ((u < 32) == (v < 32)) ? 1.0f : -1.0f;
}

// Pairwise reciprocal: 2 terms share one rcp.
//   w = rcp(d0*d1);  acc += (n0*d1 + n1*d0) * w
// If D==0 the pair is skipped (expected ~4 events total, <=2.4e-5 abs on a
// ~6.25 result -- negligible vs 1e-3 tolerance).
#define TERM2P(AU0,SU0,CU0,AV0,SV0,CV0,AU1,SU1,CU1,AV1,SV1,CV1,ACC) do { \
    float d0_ = (AU0) - (AV0);                                 \
    float d1_ = (AU1) - (AV1);                                 \
    float D_  = d0_ * d1_;                                     \
    float w_  = frcp(D_);                                      \
    float t0_ = (CU0) * (SV0);                                 \
    float n0_ = fmaf((SU0), (CV0), -t0_);                      \
    float t1_ = (CU1) * (SV1);                                 \
    float n1_ = fmaf((SU1), (CV1), -t1_);                      \
    float s_  = n0_ * d1_;                                     \
    s_ = fmaf(n1_, d0_, s_);                                   \
    if (D_ != 0.0f) (ACC) = fmaf(s_, w_, (ACC));               \
} while (0)

#define TERM4(AU,SU,CU,AV,SV,CV,ACC) do {                      \
    TERM2P((AU).x,(SU).x,(CU).x,(AV).x,(SV).x,(CV).x,          \
           (AU).y,(SU).y,(CU).y,(AV).y,(SV).y,(CV).y,(ACC));   \
    TERM2P((AU).z,(SU).z,(CU).z,(AV).z,(SV).z,(CV).z,          \
           (AU).w,(SU).w,(CU).w,(AV).w,(SV).w,(CV).w,(ACC));   \
} while (0)

// ============================================================================
// Fused kernel: phase 1 pools this block's 128-k slice of all 64 rows into
// smem (a, s, c); phase 2 computes all 10 tile-pairs over the slice.
// No cp.async, no stage barriers, single wave (256 blocks <= 296 slots).
// ============================================================================
__global__ void __launch_bounds__(256, 2) fused_kernel(
    const float* __restrict__ A, const float* __restrict__ B,
    float* __restrict__ out) {
    extern __shared__ __align__(16) float sm[];
    __shared__ double red[8];
    __shared__ int s_last;
    const int tid = threadIdx.x;
    const int kc = blockIdx.x;

    // ---------------- phase 1: pool + sincos into smem ----------------
    // 8192 outputs (64 rows x 128 feats), 32 per thread.
    // Lanes map to consecutive fidx -> 16 lanes x 16B contiguous raw loads.
    #pragma unroll 4
    for (int i = 0; i < 32; ++i) {
        const int o = i * 256 + tid;
        const int row  = o >> 7;          // 0..63
        const int fidx = o & 127;         // k index within chunk
        const int f = kc * KCH + fidx;    // global pooled feature
        const int tensor = row >> 5, b = row & 31;
        const int c = f >> 8, ph = (f >> 4) & 15, pw = f & 15;
        const float* src = tensor ? B : A;
        const float* p = src + ((((b * 128 + c) * 64) + ph * 4) * 64 + pw * 4);
        float4 v0 = __ldcs((const float4*)(p));
        float4 v1 = __ldcs((const float4*)(p + 64));
        float4 v2 = __ldcs((const float4*)(p + 128));
        float4 v3 = __ldcs((const float4*)(p + 192));
        float sum = (((v0.x + v0.y) + (v0.z + v0.w))
                  +  ((v1.x + v1.y) + (v1.z + v1.w)))
                  + (((v2.x + v2.y) + (v2.z + v2.w))
                  +  ((v3.x + v3.y) + (v3.z + v3.w)));
        float m = sum * 0.0625f;
        float s, cc;
        sincos_fast(100.0f * m, s, cc);
        const int off = row * ROWSTR + fidx;
        sm[off]              = m;
        sm[ARRSTR + off]     = s;
        sm[2 * ARRSTR + off] = cc;
    }
    __syncthreads();

    // ---------------- phase 2: 10 tile-pairs over the slice ----------------
    const int kq = tid >> 4;             // 0..15 -> float4 slot (+16 for h=1)
    const int tu = (tid >> 2) & 3;       // 0..3
    const int tv = tid & 3;              // 0..3
    float tot = 0.0f;

    #pragma unroll 1
    for (int pidx = 0; pidx < 10; ++pidx) {
        const int Ibase = c_PI[pidx] * 16, Jbase = c_PJ[pidx] * 16;
        float acc[4][4];
        #pragma unroll
        for (int i = 0; i < 4; ++i)
            #pragma unroll
            for (int j = 0; j < 4; ++j) acc[i][j] = 0.0f;

        #pragma unroll
        for (int h = 0; h < 2; ++h) {
            const float* base = sm + (kq + 16 * h) * 4;
            float4 av[4], sv[4], cv[4];
            #pragma unroll
            for (int j = 0; j < 4; ++j) {
                const int vo = (Jbase + tv + 4 * j) * ROWSTR;
                av[j] = *(const float4*)(base + vo);
                sv[j] = *(const float4*)(base + ARRSTR + vo);
                cv[j] = *(const float4*)(base + 2 * ARRSTR + vo);
            }
            #pragma unroll
            for (int i = 0; i < 4; ++i) {
                const int uo = (Ibase + tu + 4 * i) * ROWSTR;
                float4 au = *(const float4*)(base + uo);
                float4 su = *(const float4*)(base + ARRSTR + uo);
                float4 cu = *(const float4*)(base + 2 * ARRSTR + uo);
                #pragma unroll
                for (int j = 0; j < 4; ++j)
                    TERM4(au, su, cu, av[j], sv[j], cv[j], acc[i][j]);
            }
        }

        const bool diag = (Ibase == Jbase);
        #pragma unroll
        for (int i = 0; i < 4; ++i) {
            const int u = Ibase + tu + 4 * i;
            #pragma unroll
            for (int j = 0; j < 4; ++j) {
                const int v = Jbase + tv + 4 * j;
                tot += wgt(u, v, diag) * acc[i][j];
            }
        }
    }

    // ---------------- block reduction (deterministic, double) --------------
    double td = (double)tot;
    #pragma unroll
    for (int off = 16; off; off >>= 1)
        td += __shfl_down_sync(0xffffffffu, td, off);
    const int warp = tid >> 5, lane = tid & 31;
    if (lane == 0) red[warp] = td;
    __syncthreads();
    if (tid == 0) {
        double ss = 0.0;
        #pragma unroll
        for (int i = 0; i < 8; ++i) ss += red[i];
        g_part[kc] = ss;
        __threadfence();
        unsigned old = atomicInc(&g_ctr, NBLK - 1);   // wraps -> replay-safe
        s_last = (old == NBLK - 1) ? 1 : 0;
    }
    __syncthreads();

    // last-arriving block: fixed-order final reduction
    if (s_last) {
        double s = (tid < NBLK) ? g_part[tid] : 0.0;
        #pragma unroll
        for (int off = 16; off; off >>= 1)
            s += __shfl_down_sync(0xffffffffu, s, off);
        if (lane == 0) red[warp] = s;
        __syncthreads();
        if (tid == 0) {
            double t = 0.0;
            #pragma unroll
            for (int i = 0; i < 8; ++i) t += red[i];
            // result = 6.25 (diagonal, 2*32*T/1024) + 2/(1024*32768) * signed sum
            out[0] = (float)(6.25 + t * (2.0 / 33554432.0));
        }
    }
}

// ---------------- launch ------------------------------------------------------
extern "C" void kernel_launch(void* const* d_in, const int* in_sizes, int n_in,
                              void* d_out, int out_size) {
    (void)in_sizes; (void)n_in; (void)out_size;
    const float* A = (const float*)d_in[0];
    const float* B = (const float*)d_in[1];
    static int attr_set = 0;
    if (!attr_set) {
        cudaFuncSetAttribute(fused_kernel,
                             cudaFuncAttributeMaxDynamicSharedMemorySize,
                             SMEM_BYTES);
        attr_set = 1;
    }
    fused_kernel<<<NBLK, 256, SMEM_BYTES>>>(A, B, (float*)d_out);
}

// round 13
// speedup vs baseline: 1.4680x; 1.1047x over previous
#include <cuda_runtime.h>
#include <cstdint>

#define NBLK   512            /* one block per 64-k chunk */
#define KCH    64
#define ROWSTR 72             /* 64 data + 8 pad; 72 mod 32 = 8 -> conflict-free */
#define ARRSTR (64 * ROWSTR)  /* 4608 floats per array */
#define SMEM_BYTES (3 * ARRSTR * 4)   /* 55296 B: a, s, c for 64 rows x 64 k */

__device__ double g_part[NBLK];
__device__ unsigned g_ctr = 0;   // atomicInc wraps back to 0 -> graph-replay safe

__constant__ int c_PI[10] = {0,0,0,0,1,1,1,2,2,3};
__constant__ int c_PJ[10] = {0,1,2,3,1,2,3,2,3,3};

// ---------------- fast fp32 sincos(x), |x| <~ 1000 --------------------------
__device__ __forceinline__ void sincos_fast(float x, float& s_out, float& c_out) {
    const float PIO2_A = 1.5707963705062866f;      // RN(pi/2)
    const float PIO2_B = -4.3711388286737929e-8f;  // pi/2 - PIO2_A
    float q = rintf(x * 0.63661977236758134f);     // 2/pi
    int qi = (int)q;
    float r = fmaf(q, -PIO2_A, x);
    r = fmaf(q, -PIO2_B, r);
    float z = r * r;
    float ps = fmaf(z, fmaf(z, -1.9515295891e-4f, 8.3321608736e-3f), -1.6666654611e-1f);
    float sinr = fmaf(r * z, ps, r);
    float pc = fmaf(z, fmaf(z, 2.443315711809948e-5f, -1.388731625493765e-3f),
                    4.166664568298827e-2f);
    float cosr = fmaf(z * z, pc, fmaf(z, -0.5f, 1.0f));
    float s, c;
    if (qi & 1) { s = cosr; c = -sinr; } else { s = sinr; c = cosr; }
    if (qi & 2) { s = -s; c = -c; }
    s_out = s; c_out = c;
}

__device__ __forceinline__ float frcp(float x) {
    float r; asm("rcp.approx.ftz.f32 %0, %1;" : "=f"(r) : "f"(x)); return r;
}
__device__ __forceinline__ float wgt(int u, int v, bool diag) {
    if (diag && u >= v) return 0.0f;
    return ((u < 32) == (v < 32)) ? 1.0f : -1.0f;
}

// Pairwise reciprocal: 2 terms share one rcp.
//   w = rcp(d0*d1);  acc += (n0*d1 + n1*d0) * w
// If D==0 the pair is skipped (expected ~4 events total, <=2.4e-5 abs on a
// ~6.25 result -- negligible vs 1e-3 tolerance).
#define TERM2P(AU0,SU0,CU0,AV0,SV0,CV0,AU1,SU1,CU1,AV1,SV1,CV1,ACC) do { \
    float d0_ = (AU0) - (AV0);                                 \
    float d1_ = (AU1) - (AV1);                                 \
    float D_  = d0_ * d1_;                                     \
    float w_  = frcp(D_);                                      \
    float t0_ = (CU0) * (SV0);                                 \
    float n0_ = fmaf((SU0), (CV0), -t0_);                      \
    float t1_ = (CU1) * (SV1);                                 \
    float n1_ = fmaf((SU1), (CV1), -t1_);                      \
    float s_  = n0_ * d1_;                                     \
    s_ = fmaf(n1_, d0_, s_);                                   \
    if (D_ != 0.0f) (ACC) = fmaf(s_, w_, (ACC));               \
} while (0)

#define TERM4(AU,SU,CU,AV,SV,CV,ACC) do {                      \
    TERM2P((AU).x,(SU).x,(CU).x,(AV).x,(SV).x,(CV).x,          \
           (AU).y,(SU).y,(CU).y,(AV).y,(SV).y,(CV).y,(ACC));   \
    TERM2P((AU).z,(SU).z,(CU).z,(AV).z,(SV).z,(CV).z,          \
           (AU).w,(SU).w,(CU).w,(AV).w,(SV).w,(CV).w,(ACC));   \
} while (0)

// ============================================================================
// Fused kernel: phase 1 pools this block's 64-k slice of all 64 rows into
// smem (a, s, c); phase 2 computes all 10 tile-pairs over the slice.
// Grid 512 (3.46 blocks/SM, 2 resident) -> work-stealing staggers block
// starts, overlapping one block's DRAM phase with the other's FMA phase.
// ============================================================================
__global__ void __launch_bounds__(256, 2) fused_kernel(
    const float* __restrict__ A, const float* __restrict__ B,
    float* __restrict__ out) {
    extern __shared__ __align__(16) float sm[];
    __shared__ double red[8];
    __shared__ int s_last;
    const int tid = threadIdx.x;
    const int kc = blockIdx.x;

    // ---------------- phase 1: pool + sincos into smem ----------------
    // 4096 outputs (64 rows x 64 feats), 16 per thread.
    #pragma unroll 4
    for (int i = 0; i < 16; ++i) {
        const int o = i * 256 + tid;
        const int row  = o >> 6;          // 0..63
        const int fidx = o & 63;          // k index within chunk
        const int f = kc * KCH + fidx;    // global pooled feature
        const int tensor = row >> 5, b = row & 31;
        const int c = f >> 8, ph = (f >> 4) & 15, pw = f & 15;
        const float* src = tensor ? B : A;
        const float* p = src + ((((b * 128 + c) * 64) + ph * 4) * 64 + pw * 4);
        float4 v0 = __ldcs((const float4*)(p));
        float4 v1 = __ldcs((const float4*)(p + 64));
        float4 v2 = __ldcs((const float4*)(p + 128));
        float4 v3 = __ldcs((const float4*)(p + 192));
        float sum = (((v0.x + v0.y) + (v0.z + v0.w))
                  +  ((v1.x + v1.y) + (v1.z + v1.w)))
                  + (((v2.x + v2.y) + (v2.z + v2.w))
                  +  ((v3.x + v3.y) + (v3.z + v3.w)));
        float m = sum * 0.0625f;
        float s, cc;
        sincos_fast(100.0f * m, s, cc);
        const int off = row * ROWSTR + fidx;
        sm[off]              = m;
        sm[ARRSTR + off]     = s;
        sm[2 * ARRSTR + off] = cc;
    }
    __syncthreads();

    // ---------------- phase 2: 10 tile-pairs over the slice ----------------
    const int kq = tid >> 4;             // 0..15 -> float4 slot (covers 64 k)
    const int tu = (tid >> 2) & 3;       // 0..3
    const int tv = tid & 3;              // 0..3
    float tot = 0.0f;

    #pragma unroll 1
    for (int pidx = 0; pidx < 10; ++pidx) {
        const int Ibase = c_PI[pidx] * 16, Jbase = c_PJ[pidx] * 16;
        float acc[4][4];
        #pragma unroll
        for (int i = 0; i < 4; ++i)
            #pragma unroll
            for (int j = 0; j < 4; ++j) acc[i][j] = 0.0f;

        const float* base = sm + kq * 4;
        float4 av[4], sv[4], cv[4];
        #pragma unroll
        for (int j = 0; j < 4; ++j) {
            const int vo = (Jbase + tv + 4 * j) * ROWSTR;
            av[j] = *(const float4*)(base + vo);
            sv[j] = *(const float4*)(base + ARRSTR + vo);
            cv[j] = *(const float4*)(base + 2 * ARRSTR + vo);
        }
        #pragma unroll
        for (int i = 0; i < 4; ++i) {
            const int uo = (Ibase + tu + 4 * i) * ROWSTR;
            float4 au = *(const float4*)(base + uo);
            float4 su = *(const float4*)(base + ARRSTR + uo);
            float4 cu = *(const float4*)(base + 2 * ARRSTR + uo);
            #pragma unroll
            for (int j = 0; j < 4; ++j)
                TERM4(au, su, cu, av[j], sv[j], cv[j], acc[i][j]);
        }

        const bool diag = (Ibase == Jbase);
        #pragma unroll
        for (int i = 0; i < 4; ++i) {
            const int u = Ibase + tu + 4 * i;
            #pragma unroll
            for (int j = 0; j < 4; ++j) {
                const int v = Jbase + tv + 4 * j;
                tot += wgt(u, v, diag) * acc[i][j];
            }
        }
    }

    // ---------------- block reduction (deterministic, double) --------------
    double td = (double)tot;
    #pragma unroll
    for (int off = 16; off; off >>= 1)
        td += __shfl_down_sync(0xffffffffu, td, off);
    const int warp = tid >> 5, lane = tid & 31;
    if (lane == 0) red[warp] = td;
    __syncthreads();
    if (tid == 0) {
        double ss = 0.0;
        #pragma unroll
        for (int i = 0; i < 8; ++i) ss += red[i];
        g_part[kc] = ss;
        __threadfence();
        unsigned old = atomicInc(&g_ctr, NBLK - 1);   // wraps -> replay-safe
        s_last = (old == NBLK - 1) ? 1 : 0;
    }
    __syncthreads();

    // last-arriving block: fixed-order final reduction
    if (s_last) {
        double s = g_part[tid] + g_part[tid + 256];
        #pragma unroll
        for (int off = 16; off; off >>= 1)
            s += __shfl_down_sync(0xffffffffu, s, off);
        if (lane == 0) red[warp] = s;
        __syncthreads();
        if (tid == 0) {
            double t = 0.0;
            #pragma unroll
            for (int i = 0; i < 8; ++i) t += red[i];
            // result = 6.25 (diagonal, 2*32*T/1024) + 2/(1024*32768) * signed sum
            out[0] = (float)(6.25 + t * (2.0 / 33554432.0));
        }
    }
}

// ---------------- launch ------------------------------------------------------
extern "C" void kernel_launch(void* const* d_in, const int* in_sizes, int n_in,
                              void* d_out, int out_size) {
    (void)in_sizes; (void)n_in; (void)out_size;
    const float* A = (const float*)d_in[0];
    const float* B = (const float*)d_in[1];
    static int attr_set = 0;
    if (!attr_set) {
        cudaFuncSetAttribute(fused_kernel,
                             cudaFuncAttributeMaxDynamicSharedMemorySize,
                             SMEM_BYTES);
        attr_set = 1;
    }
    fused_kernel<<<NBLK, 256, SMEM_BYTES>>>(A, B, (float*)d_out);
}

// round 14
// speedup vs baseline: 1.4817x; 1.0093x over previous
#include <cuda_runtime.h>
#include <cstdint>

#define NBLK   1024           /* one block per 32-k chunk */
#define KCH    32
#define ROWSTR 40             /* 32 data + 8 pad; 40 mod 32 = 8 -> conflict-free */
#define ARRSTR (64 * ROWSTR)  /* 2560 floats per array */
#define SMEM_BYTES (3 * ARRSTR * 4)   /* 30720 B: a, s, c for 64 rows x 32 k */

__device__ double g_part[NBLK];
__device__ unsigned g_ctr = 0;   // atomicInc wraps back to 0 -> graph-replay safe

__constant__ int c_PI[10] = {0,0,0,0,1,1,1,2,2,3};
__constant__ int c_PJ[10] = {0,1,2,3,1,2,3,2,3,3};

// ---------------- fast fp32 sincos(x), |x| <~ 1000 --------------------------
__device__ __forceinline__ void sincos_fast(float x, float& s_out, float& c_out) {
    const float PIO2_A = 1.5707963705062866f;      // RN(pi/2)
    const float PIO2_B = -4.3711388286737929e-8f;  // pi/2 - PIO2_A
    float q = rintf(x * 0.63661977236758134f);     // 2/pi
    int qi = (int)q;
    float r = fmaf(q, -PIO2_A, x);
    r = fmaf(q, -PIO2_B, r);
    float z = r * r;
    float ps = fmaf(z, fmaf(z, -1.9515295891e-4f, 8.3321608736e-3f), -1.6666654611e-1f);
    float sinr = fmaf(r * z, ps, r);
    float pc = fmaf(z, fmaf(z, 2.443315711809948e-5f, -1.388731625493765e-3f),
                    4.166664568298827e-2f);
    float cosr = fmaf(z * z, pc, fmaf(z, -0.5f, 1.0f));
    float s, c;
    if (qi & 1) { s = cosr; c = -sinr; } else { s = sinr; c = cosr; }
    if (qi & 2) { s = -s; c = -c; }
    s_out = s; c_out = c;
}

__device__ __forceinline__ float frcp(float x) {
    float r; asm("rcp.approx.ftz.f32 %0, %1;" : "=f"(r) : "f"(x)); return r;
}
__device__ __forceinline__ float wgt(int u, int v, bool diag) {
    if (diag && u >= v) return 0.0f;
    return ((u < 32) == (v < 32)) ? 1.0f : -1.0f;
}

// Pairwise reciprocal: 2 terms share one rcp.
//   w = rcp(d0*d1);  acc += (n0*d1 + n1*d0) * w
// If D==0 the pair is skipped (expected ~4 events total, <=2.4e-5 abs on a
// ~6.25 result -- negligible vs 1e-3 tolerance).
#define TERM2P(AU0,SU0,CU0,AV0,SV0,CV0,AU1,SU1,CU1,AV1,SV1,CV1,ACC) do { \
    float d0_ = (AU0) - (AV0);                                 \
    float d1_ = (AU1) - (AV1);                                 \
    float D_  = d0_ * d1_;                                     \
    float w_  = frcp(D_);                                      \
    float t0_ = (CU0) * (SV0);                                 \
    float n0_ = fmaf((SU0), (CV0), -t0_);                      \
    float t1_ = (CU1) * (SV1);                                 \
    float n1_ = fmaf((SU1), (CV1), -t1_);                      \
    float s_  = n0_ * d1_;                                     \
    s_ = fmaf(n1_, d0_, s_);                                   \
    if (D_ != 0.0f) (ACC) = fmaf(s_, w_, (ACC));               \
} while (0)

#define TERM4(AU,SU,CU,AV,SV,CV,ACC) do {                      \
    TERM2P((AU).x,(SU).x,(CU).x,(AV).x,(SV).x,(CV).x,          \
           (AU).y,(SU).y,(CU).y,(AV).y,(SV).y,(CV).y,(ACC));   \
    TERM2P((AU).z,(SU).z,(CU).z,(AV).z,(SV).z,(CV).z,          \
           (AU).w,(SU).w,(CU).w,(AV).w,(SV).w,(CV).w,(ACC));   \
} while (0)

// ============================================================================
// Fused kernel, fine granularity: each block pools a 32-k slice of all 64
// rows into smem, then computes all 10 tile-pairs over it. 1024 blocks
// (~6.9 per SM slot pair) -> resident blocks desync quickly, overlapping
// one block's DRAM phase with the other's FMA phase for most of the run.
// ============================================================================
__global__ void __launch_bounds__(256, 2) fused_kernel(
    const float* __restrict__ A, const float* __restrict__ B,
    float* __restrict__ out) {
    extern __shared__ __align__(16) float sm[];
    __shared__ double red[8];
    __shared__ int s_last;
    const int tid = threadIdx.x;
    const int kc = blockIdx.x;

    // ---------------- phase 1: pool + sincos into smem ----------------
    // 2048 outputs (64 rows x 32 feats), 8 per thread.
    #pragma unroll 4
    for (int i = 0; i < 8; ++i) {
        const int o = i * 256 + tid;
        const int row  = o >> 5;          // 0..63
        const int fidx = o & 31;          // k index within chunk
        const int f = kc * KCH + fidx;    // global pooled feature
        const int tensor = row >> 5, b = row & 31;
        const int c = f >> 8, ph = (f >> 4) & 15, pw = f & 15;
        const float* src = tensor ? B : A;
        const float* p = src + ((((b * 128 + c) * 64) + ph * 4) * 64 + pw * 4);
        float4 v0 = __ldcs((const float4*)(p));
        float4 v1 = __ldcs((const float4*)(p + 64));
        float4 v2 = __ldcs((const float4*)(p + 128));
        float4 v3 = __ldcs((const float4*)(p + 192));
        float sum = (((v0.x + v0.y) + (v0.z + v0.w))
                  +  ((v1.x + v1.y) + (v1.z + v1.w)))
                  + (((v2.x + v2.y) + (v2.z + v2.w))
                  +  ((v3.x + v3.y) + (v3.z + v3.w)));
        float m = sum * 0.0625f;
        float s, cc;
        sincos_fast(100.0f * m, s, cc);
        const int off = row * ROWSTR + fidx;
        sm[off]              = m;
        sm[ARRSTR + off]     = s;
        sm[2 * ARRSTR + off] = cc;
    }
    __syncthreads();

    // ---------------- phase 2: 10 tile-pairs over the slice ----------------
    // tid bits: [0:2)=tv, [2:5)=tu, [5:8)=kq (one kq per warp).
    const int kq = tid >> 5;             // 0..7 -> float4 slot (covers 32 k)
    const int tu = (tid >> 2) & 7;       // 0..7
    const int tv = tid & 3;              // 0..3
    float tot = 0.0f;

    #pragma unroll 1
    for (int pidx = 0; pidx < 10; ++pidx) {
        const int Ibase = c_PI[pidx] * 16, Jbase = c_PJ[pidx] * 16;
        float acc[2][4];
        #pragma unroll
        for (int i = 0; i < 2; ++i)
            #pragma unroll
            for (int j = 0; j < 4; ++j) acc[i][j] = 0.0f;

        const float* base = sm + kq * 4;
        float4 av[4], sv[4], cv[4];
        #pragma unroll
        for (int j = 0; j < 4; ++j) {
            const int vo = (Jbase + tv + 4 * j) * ROWSTR;
            av[j] = *(const float4*)(base + vo);
            sv[j] = *(const float4*)(base + ARRSTR + vo);
            cv[j] = *(const float4*)(base + 2 * ARRSTR + vo);
        }
        #pragma unroll
        for (int i = 0; i < 2; ++i) {
            const int uo = (Ibase + tu + 8 * i) * ROWSTR;
            float4 au = *(const float4*)(base + uo);
            float4 su = *(const float4*)(base + ARRSTR + uo);
            float4 cu = *(const float4*)(base + 2 * ARRSTR + uo);
            #pragma unroll
            for (int j = 0; j < 4; ++j)
                TERM4(au, su, cu, av[j], sv[j], cv[j], acc[i][j]);
        }

        const bool diag = (Ibase == Jbase);
        #pragma unroll
        for (int i = 0; i < 2; ++i) {
            const int u = Ibase + tu + 8 * i;
            #pragma unroll
            for (int j = 0; j < 4; ++j) {
                const int v = Jbase + tv + 4 * j;
                tot += wgt(u, v, diag) * acc[i][j];
            }
        }
    }

    // ---------------- block reduction (deterministic, double) --------------
    double td = (double)tot;
    #pragma unroll
    for (int off = 16; off; off >>= 1)
        td += __shfl_down_sync(0xffffffffu, td, off);
    const int warp = tid >> 5, lane = tid & 31;
    if (lane == 0) red[warp] = td;
    __syncthreads();
    if (tid == 0) {
        double ss = 0.0;
        #pragma unroll
        for (int i = 0; i < 8; ++i) ss += red[i];
        g_part[kc] = ss;
        __threadfence();
        unsigned old = atomicInc(&g_ctr, NBLK - 1);   // wraps -> replay-safe
        s_last = (old == NBLK - 1) ? 1 : 0;
    }
    __syncthreads();

    // last-arriving block: fixed-order final reduction
    if (s_last) {
        double s = (g_part[tid] + g_part[tid + 256])
                 + (g_part[tid + 512] + g_part[tid + 768]);
        #pragma unroll
        for (int off = 16; off; off >>= 1)
            s += __shfl_down_sync(0xffffffffu, s, off);
        if (lane == 0) red[warp] = s;
        __syncthreads();
        if (tid == 0) {
            double t = 0.0;
            #pragma unroll
            for (int i = 0; i < 8; ++i) t += red[i];
            // result = 6.25 (diagonal, 2*32*T/1024) + 2/(1024*32768) * signed sum
            out[0] = (float)(6.25 + t * (2.0 / 33554432.0));
        }
    }
}

// ---------------- launch ------------------------------------------------------
extern "C" void kernel_launch(void* const* d_in, const int* in_sizes, int n_in,
                              void* d_out, int out_size) {
    (void)in_sizes; (void)n_in; (void)out_size;
    const float* A = (const float*)d_in[0];
    const float* B = (const float*)d_in[1];
    static int attr_set = 0;
    if (!attr_set) {
        cudaFuncSetAttribute(fused_kernel,
                             cudaFuncAttributeMaxDynamicSharedMemorySize,
                             SMEM_BYTES);
        attr_set = 1;
    }
    fused_kernel<<<NBLK, 256, SMEM_BYTES>>>(A, B, (float*)d_out);
}

// round 15
// speedup vs baseline: 1.6660x; 1.1244x over previous
#include <cuda_runtime.h>
#include <cstdint>

#define NBLK   2048           /* one block per 16-k chunk */
#define KCH    16
#define ROWSTR 20             /* 16 data + 4 pad; 80B rows -> conflict-free mod 128B */
#define ARRSTR (64 * ROWSTR)  /* 1280 floats per array */
#define SMEM_BYTES (3 * ARRSTR * 4)   /* 15360 B: a, s, c for 64 rows x 16 k */

__device__ double g_part[NBLK];
__device__ unsigned g_ctr = 0;   // atomicInc wraps back to 0 -> graph-replay safe

__constant__ int c_PI[10] = {0,0,0,0,1,1,1,2,2,3};
__constant__ int c_PJ[10] = {0,1,2,3,1,2,3,2,3,3};

// ---------------- fast fp32 sincos(x), |x| <~ 1000 --------------------------
__device__ __forceinline__ void sincos_fast(float x, float& s_out, float& c_out) {
    const float PIO2_A = 1.5707963705062866f;      // RN(pi/2)
    const float PIO2_B = -4.3711388286737929e-8f;  // pi/2 - PIO2_A
    float q = rintf(x * 0.63661977236758134f);     // 2/pi
    int qi = (int)q;
    float r = fmaf(q, -PIO2_A, x);
    r = fmaf(q, -PIO2_B, r);
    float z = r * r;
    float ps = fmaf(z, fmaf(z, -1.9515295891e-4f, 8.3321608736e-3f), -1.6666654611e-1f);
    float sinr = fmaf(r * z, ps, r);
    float pc = fmaf(z, fmaf(z, 2.443315711809948e-5f, -1.388731625493765e-3f),
                    4.166664568298827e-2f);
    float cosr = fmaf(z * z, pc, fmaf(z, -0.5f, 1.0f));
    float s, c;
    if (qi & 1) { s = cosr; c = -sinr; } else { s = sinr; c = cosr; }
    if (qi & 2) { s = -s; c = -c; }
    s_out = s; c_out = c;
}

__device__ __forceinline__ float frcp(float x) {
    float r; asm("rcp.approx.ftz.f32 %0, %1;" : "=f"(r) : "f"(x)); return r;
}
__device__ __forceinline__ float wgt(int u, int v, bool diag) {
    if (diag && u >= v) return 0.0f;
    return ((u < 32) == (v < 32)) ? 1.0f : -1.0f;
}

// Pairwise reciprocal: 2 terms share one rcp.
//   w = rcp(d0*d1);  acc += (n0*d1 + n1*d0) * w
// If D==0 the pair is skipped (expected ~4 events total, <=2.4e-5 abs on a
// ~6.25 result -- negligible vs 1e-3 tolerance).
#define TERM2P(AU0,SU0,CU0,AV0,SV0,CV0,AU1,SU1,CU1,AV1,SV1,CV1,ACC) do { \
    float d0_ = (AU0) - (AV0);                                 \
    float d1_ = (AU1) - (AV1);                                 \
    float D_  = d0_ * d1_;                                     \
    float w_  = frcp(D_);                                      \
    float t0_ = (CU0) * (SV0);                                 \
    float n0_ = fmaf((SU0), (CV0), -t0_);                      \
    float t1_ = (CU1) * (SV1);                                 \
    float n1_ = fmaf((SU1), (CV1), -t1_);                      \
    float s_  = n0_ * d1_;                                     \
    s_ = fmaf(n1_, d0_, s_);                                   \
    if (D_ != 0.0f) (ACC) = fmaf(s_, w_, (ACC));               \
} while (0)

#define TERM4(AU,SU,CU,AV,SV,CV,ACC) do {                      \
    TERM2P((AU).x,(SU).x,(CU).x,(AV).x,(SV).x,(CV).x,          \
           (AU).y,(SU).y,(CU).y,(AV).y,(SV).y,(CV).y,(ACC));   \
    TERM2P((AU).z,(SU).z,(CU).z,(AV).z,(SV).z,(CV).z,          \
           (AU).w,(SU).w,(CU).w,(AV).w,(SV).w,(CV).w,(ACC));   \
} while (0)

// ============================================================================
// Fused kernel, 128-thread blocks, 5 resident per SM (no register cap
// needed: natural ~96 regs <= 102). Five independent pool/compute phases
// per SM interleave DRAM and FMA bursts; 20 warps/SM hide latency.
// ============================================================================
__global__ void __launch_bounds__(128, 5) fused_kernel(
    const float* __restrict__ A, const float* __restrict__ B,
    float* __restrict__ out) {
    extern __shared__ __align__(16) float sm[];
    __shared__ double red[4];
    __shared__ int s_last;
    const int tid = threadIdx.x;
    const int kc = blockIdx.x;

    // ---------------- phase 1: pool + sincos into smem ----------------
    // 1024 outputs (64 rows x 16 feats), 8 per thread.
    #pragma unroll 4
    for (int i = 0; i < 8; ++i) {
        const int o = i * 128 + tid;
        const int row  = o >> 4;          // 0..63
        const int fidx = o & 15;          // k index within chunk
        const int f = kc * KCH + fidx;    // global pooled feature
        const int tensor = row >> 5, b = row & 31;
        const int c = f >> 8, ph = (f >> 4) & 15, pw = f & 15;
        const float* src = tensor ? B : A;
        const float* p = src + ((((b * 128 + c) * 64) + ph * 4) * 64 + pw * 4);
        float4 v0 = __ldcs((const float4*)(p));
        float4 v1 = __ldcs((const float4*)(p + 64));
        float4 v2 = __ldcs((const float4*)(p + 128));
        float4 v3 = __ldcs((const float4*)(p + 192));
        float sum = (((v0.x + v0.y) + (v0.z + v0.w))
                  +  ((v1.x + v1.y) + (v1.z + v1.w)))
                  + (((v2.x + v2.y) + (v2.z + v2.w))
                  +  ((v3.x + v3.y) + (v3.z + v3.w)));
        float m = sum * 0.0625f;
        float s, cc;
        sincos_fast(100.0f * m, s, cc);
        const int off = row * ROWSTR + fidx;
        sm[off]              = m;
        sm[ARRSTR + off]     = s;
        sm[2 * ARRSTR + off] = cc;
    }
    __syncthreads();

    // ---------------- phase 2: 10 tile-pairs over the slice ----------------
    // tid bits: [0:2)=tv, [2:5)=tu, [5:7)=kq (one float4 slot per warp).
    const int kq = tid >> 5;             // 0..3 -> float4 slot (covers 16 k)
    const int tu = (tid >> 2) & 7;       // 0..7
    const int tv = tid & 3;              // 0..3
    float tot = 0.0f;

    #pragma unroll 1
    for (int pidx = 0; pidx < 10; ++pidx) {
        const int Ibase = c_PI[pidx] * 16, Jbase = c_PJ[pidx] * 16;
        float acc[2][4];
        #pragma unroll
        for (int i = 0; i < 2; ++i)
            #pragma unroll
            for (int j = 0; j < 4; ++j) acc[i][j] = 0.0f;

        const float* base = sm + kq * 4;
        float4 av[4], sv[4], cv[4];
        #pragma unroll
        for (int j = 0; j < 4; ++j) {
            const int vo = (Jbase + tv + 4 * j) * ROWSTR;
            av[j] = *(const float4*)(base + vo);
            sv[j] = *(const float4*)(base + ARRSTR + vo);
            cv[j] = *(const float4*)(base + 2 * ARRSTR + vo);
        }
        #pragma unroll
        for (int i = 0; i < 2; ++i) {
            const int uo = (Ibase + tu + 8 * i) * ROWSTR;
            float4 au = *(const float4*)(base + uo);
            float4 su = *(const float4*)(base + ARRSTR + uo);
            float4 cu = *(const float4*)(base + 2 * ARRSTR + uo);
            #pragma unroll
            for (int j = 0; j < 4; ++j)
                TERM4(au, su, cu, av[j], sv[j], cv[j], acc[i][j]);
        }

        const bool diag = (Ibase == Jbase);
        #pragma unroll
        for (int i = 0; i < 2; ++i) {
            const int u = Ibase + tu + 8 * i;
            #pragma unroll
            for (int j = 0; j < 4; ++j) {
                const int v = Jbase + tv + 4 * j;
                tot += wgt(u, v, diag) * acc[i][j];
            }
        }
    }

    // ---------------- block reduction (deterministic, double) --------------
    double td = (double)tot;
    #pragma unroll
    for (int off = 16; off; off >>= 1)
        td += __shfl_down_sync(0xffffffffu, td, off);
    const int warp = tid >> 5, lane = tid & 31;
    if (lane == 0) red[warp] = td;
    __syncthreads();
    if (tid == 0) {
        double ss = ((red[0] + red[1]) + (red[2] + red[3]));
        g_part[kc] = ss;
        __threadfence();
        unsigned old = atomicInc(&g_ctr, NBLK - 1);   // wraps -> replay-safe
        s_last = (old == NBLK - 1) ? 1 : 0;
    }
    __syncthreads();

    // last-arriving block: fixed-order final reduction
    if (s_last) {
        double s = 0.0;
        #pragma unroll
        for (int i = 0; i < 16; ++i) s += g_part[i * 128 + tid];
        #pragma unroll
        for (int off = 16; off; off >>= 1)
            s += __shfl_down_sync(0xffffffffu, s, off);
        if (lane == 0) red[warp] = s;
        __syncthreads();
        if (tid == 0) {
            double t = ((red[0] + red[1]) + (red[2] + red[3]));
            // result = 6.25 (diagonal, 2*32*T/1024) + 2/(1024*32768) * signed sum
            out[0] = (float)(6.25 + t * (2.0 / 33554432.0));
        }
    }
}

// ---------------- launch ------------------------------------------------------
extern "C" void kernel_launch(void* const* d_in, const int* in_sizes, int n_in,
                              void* d_out, int out_size) {
    (void)in_sizes; (void)n_in; (void)out_size;
    const float* A = (const float*)d_in[0];
    const float* B = (const float*)d_in[1];
    fused_kernel<<<NBLK, 128, SMEM_BYTES>>>(A, B, (float*)d_out);
}